// round 5
// baseline (speedup 1.0000x reference)
#include <cuda_runtime.h>
#include <cuda_bf16.h>
#include <cstdint>

// Problem constants
#define BB   2048
#define NAG  8
#define ACT  16
#define HD   32
#define HIDN 64
#define GRID_MMA 444   // 3 CTAs per SM (148 SMs)

// Scratch (__device__ globals: allowed)
__device__ float g_u[BB * NAG * HIDN];     // u[b,g,n] = base(b)+b1 - corr(b,g)  (4 MB)
__device__ float g_w1aTr[128 * HIDN];      // w1aTr[row][k] = W1[(g*48+32+a)*64 + k], row=g*16+a

// ---------------------------------------------------------------------------
// bf16 split helpers (validated): hi = truncated top 16 bits, lo = rn(residual)
// ---------------------------------------------------------------------------
__device__ __forceinline__ uint32_t pack_hi(float a, float b) {
    uint32_t r;
    asm("prmt.b32 %0, %1, %2, 0x7632;" : "=r"(r)
        : "r"(__float_as_uint(a)), "r"(__float_as_uint(b)));
    return r;
}
__device__ __forceinline__ uint32_t pack_lo(float a, float b) {
    float ha = __uint_as_float(__float_as_uint(a) & 0xffff0000u);
    float hb = __uint_as_float(__float_as_uint(b) & 0xffff0000u);
    float la = a - ha, lb = b - hb;
    uint32_t r;
    asm("cvt.rn.bf16x2.f32 %0, %1, %2;" : "=r"(r) : "f"(lb), "f"(la));
    return r;
}
__device__ __forceinline__ uint32_t smem_u32(const void* p) {
    uint32_t a;
    asm("{ .reg .u64 t; cvta.to.shared.u64 t, %1; cvt.u32.u64 %0, t; }" : "=r"(a) : "l"(p));
    return a;
}
__device__ __forceinline__ void fma4(float4& acc, float s, const float4 w) {
    acc.x = fmaf(s, w.x, acc.x);
    acc.y = fmaf(s, w.y, acc.y);
    acc.z = fmaf(s, w.z, acc.z);
    acc.w = fmaf(s, w.w, acc.w);
}

#define LDSM_X4(r, addr) \
    asm volatile("ldmatrix.sync.aligned.m8n8.x4.shared.b16 {%0,%1,%2,%3}, [%4];" \
        : "=r"((r)[0]), "=r"((r)[1]), "=r"((r)[2]), "=r"((r)[3]) : "r"(addr))
#define LDSM_X4_T(r, addr) \
    asm volatile("ldmatrix.sync.aligned.m8n8.x4.trans.shared.b16 {%0,%1,%2,%3}, [%4];" \
        : "=r"((r)[0]), "=r"((r)[1]), "=r"((r)[2]), "=r"((r)[3]) : "r"(addr))
#define MMA16816(c, a, b0, b1) \
    asm volatile("mma.sync.aligned.m16n8k16.row.col.f32.bf16.bf16.f32 " \
        "{%0,%1,%2,%3}, {%4,%5,%6,%7}, {%8,%9}, {%0,%1,%2,%3};" \
        : "+f"((c)[0]), "+f"((c)[1]), "+f"((c)[2]), "+f"((c)[3]) \
        : "r"((a)[0]), "r"((a)[1]), "r"((a)[2]), "r"((a)[3]), "r"(b0), "r"(b1))

// ---------------------------------------------------------------------------
// Kernel 1 (v3): layer-1 factorization.
// Grid 128 x 128 thr; CTA handles 16 batches. Thread = (nq, bg): nq = float4
// column group (16), bg = batch pair (8) -> 2 batches per thread (w1 reuse).
// Actions are exact one-hot: contribution = gathered W1 row (no GEMM).
// Also emits g_w1aTr (row-major action rows) for the mma build phase.
// ---------------------------------------------------------------------------
__global__ void __launch_bounds__(128) prep_kernel(
    const float* __restrict__ hidden,   // [B, 8, 32]
    const float* __restrict__ actions,  // [B, 8, 16]
    const float* __restrict__ w1,       // [384, 64]
    const float* __restrict__ b1)       // [64]
{
    __shared__ float sh[16 * 256];      // staged hidden for 16 b
    __shared__ int   sidx[16 * 8];      // one-hot indices

    const int tid = threadIdx.x;
    const int b0  = blockIdx.x * 16;
    const float4* __restrict__ w1v = reinterpret_cast<const float4*>(w1);

    if (blockIdx.x == 0) {
        // row-major action-row copy: g_w1aTr[row*64 + k] = w1[(g*48+32+a)*64 + k]
        float4* dst = reinterpret_cast<float4*>(g_w1aTr);
        #pragma unroll
        for (int e = tid; e < 128 * 16; e += 128) {
            const int row = e >> 4, q = e & 15;
            const int g = row >> 4, a = row & 15;
            dst[e] = __ldg(w1v + (g * 48 + 32 + a) * 16 + q);
        }
    }

    // stage hidden (16 b x 256 floats = 16 KB)
    {
        const float4* hv = reinterpret_cast<const float4*>(hidden + (size_t)b0 * 256);
        float4* shv = reinterpret_cast<float4*>(sh);
        #pragma unroll
        for (int e = tid; e < 1024; e += 128) shv[e] = __ldg(hv + e);
    }

    // one-hot index per (bl, g): exact (actions are {0.0, 1.0})
    {
        const int bl = tid >> 3, g = tid & 7;
        const float* ag = actions + (size_t)(b0 + bl) * 128 + g * 16;
        float s = 0.f;
        #pragma unroll
        for (int a = 0; a < ACT; ++a) s = fmaf(__ldg(ag + a), (float)a, s);
        sidx[tid] = __float2int_rn(s);
    }
    __syncthreads();

    const int nq = tid & 15;
    const int bg = tid >> 4;

    const float4 b1v = __ldg(reinterpret_cast<const float4*>(b1) + nq);
    float4 base0 = b1v, base1 = b1v;
    const float* h0 = sh + (bg * 2 + 0) * 256;
    const float* h1 = sh + (bg * 2 + 1) * 256;

    #pragma unroll 2
    for (int j = 0; j < NAG; ++j) {
        #pragma unroll
        for (int i4 = 0; i4 < 8; ++i4) {
            const int wrow = j * 48 + i4 * 4;
            const float4 w0 = __ldg(w1v + (wrow + 0) * 16 + nq);
            const float4 w1_ = __ldg(w1v + (wrow + 1) * 16 + nq);
            const float4 w2_ = __ldg(w1v + (wrow + 2) * 16 + nq);
            const float4 w3_ = __ldg(w1v + (wrow + 3) * 16 + nq);
            const float4 ha = *reinterpret_cast<const float4*>(h0 + j * 32 + i4 * 4);
            const float4 hb = *reinterpret_cast<const float4*>(h1 + j * 32 + i4 * 4);
            fma4(base0, ha.x, w0); fma4(base0, ha.y, w1_);
            fma4(base0, ha.z, w2_); fma4(base0, ha.w, w3_);
            fma4(base1, hb.x, w0); fma4(base1, hb.y, w1_);
            fma4(base1, hb.z, w2_); fma4(base1, hb.w, w3_);
        }
    }

    #pragma unroll
    for (int bi = 0; bi < 2; ++bi) {
        const int bl = bg * 2 + bi;
        const float4 base = bi ? base1 : base0;
        float4 asum[NAG];
        float4 tot = make_float4(0.f, 0.f, 0.f, 0.f);
        #pragma unroll
        for (int g = 0; g < NAG; ++g) {
            asum[g] = __ldg(w1v + (g * 48 + 32 + sidx[bl * 8 + g]) * 16 + nq);
            tot.x += asum[g].x; tot.y += asum[g].y;
            tot.z += asum[g].z; tot.w += asum[g].w;
        }
        #pragma unroll
        for (int g = 0; g < NAG; ++g) {
            float4 v;
            v.x = base.x + tot.x - asum[g].x;
            v.y = base.y + tot.y - asum[g].y;
            v.z = base.z + tot.z - asum[g].z;
            v.w = base.w + tot.w - asum[g].w;
            *reinterpret_cast<float4*>(
                &g_u[(size_t)((b0 + bl) * NAG + g) * HIDN + nq * 4]) = v;
        }
    }
}

// ---------------------------------------------------------------------------
// Kernel 2: persistent mma.sync (HMMA bf16) GEMM + fused layers 2+3.
// A' = [x_hi | x_lo | x_hi] (block2 aliases block0), B' = [W_hi; W_hi; W_lo].
// Build phase now fully vectorized: 16 LDG.128 (u) + 16 LDG.128 (w1aTr rows).
// ---------------------------------------------------------------------------
#define SM_A   0
#define SM_B   32768
#define SM_B2  57344
#define SM_W3  57600
#define SMEM_SZ 57856

__global__ void __launch_bounds__(128, 3) mma_kernel(
    const float* __restrict__ w2,   // [64, 64] (k-major)
    const float* __restrict__ b2,   // [64]
    const float* __restrict__ w3,   // [64]
    const float* __restrict__ b3,   // [1]
    float* __restrict__ out)        // [B, 128]
{
    extern __shared__ __align__(16) char dsm[];
    const uint32_t smA = smem_u32(dsm) + SM_A;
    const uint32_t smB = smem_u32(dsm) + SM_B;
    float* sb2 = reinterpret_cast<float*>(dsm + SM_B2);
    float* sw3 = reinterpret_cast<float*>(dsm + SM_W3);

    const int tid  = threadIdx.x;
    const int w    = tid >> 5;
    const int lane = tid & 31;

    if (tid < 64) {
        sb2[tid] = __ldg(b2 + tid);
        sw3[tid] = __ldg(w3 + tid);
    }
    const float b3v = __ldg(b3);

    // build B' = [W_hi; W_hi; W_lo] (192 k-rows x 64 n), xor-swizzled
    for (int e = tid; e < 192 * 32; e += 128) {
        const int kk = e >> 5;
        const int nw = e & 31;
        const int k  = kk & 63;
        const float2 f = __ldg(reinterpret_cast<const float2*>(w2 + k * 64 + 2 * nw));
        const uint32_t word = (kk < 128) ? pack_hi(f.x, f.y) : pack_lo(f.x, f.y);
        const int nc = nw >> 2;
        const uint32_t byte = (uint32_t)kk * 128u + (uint32_t)((nc ^ (kk & 7)) << 4)
                            + (uint32_t)((nw & 3) << 2);
        *reinterpret_cast<uint32_t*>(dsm + SM_B + byte) = word;
    }
    __syncthreads();

    // per-lane ldmatrix address precompute
    const int g2  = lane >> 4;
    const int gh  = (lane >> 3) & 1;
    const int lr  = lane & 7;
    const int grp = lane >> 2;
    const int tig = lane & 3;

    uint32_t aBase[2];
    #pragma unroll
    for (int mt = 0; mt < 2; ++mt)
        aBase[mt] = smA + (uint32_t)(32 * w + 16 * mt + 8 * gh + lr) * 256u;

    const int nadd = lane >> 4;
    const uint32_t bBase = smB + (uint32_t)(8 * ((lane >> 3) & 1) + lr) * 128u;
    uint32_t nxor[4];
    #pragma unroll
    for (int np = 0; np < 4; ++np)
        nxor[np] = (uint32_t)(((2 * np + nadd) ^ lr) << 4);

    const int row_ga = tid;
    const int gq     = row_ga >> 4;
    const uint32_t rbase = (uint32_t)row_ga * 256u;
    const int rx = row_ga & 7;
    const float4* __restrict__ wr =
        reinterpret_cast<const float4*>(g_w1aTr + row_ga * HIDN);

    for (int b = blockIdx.x; b < BB; b += GRID_MMA) {
        // build A': x1[row,k] = relu(u[b,g,k] + w1aTr[row,k]); hi chunks 0-7, lo 8-15
        const float4* up = reinterpret_cast<const float4*>(g_u + (size_t)(b * NAG + gq) * HIDN);
        #pragma unroll
        for (int c8 = 0; c8 < 8; ++c8) {
            const float4 u0 = __ldg(up + c8 * 2);
            const float4 u1 = __ldg(up + c8 * 2 + 1);
            const float4 w0 = __ldg(wr + c8 * 2);
            const float4 w1_ = __ldg(wr + c8 * 2 + 1);
            float x[8];
            x[0] = fmaxf(u0.x + w0.x, 0.f);  x[1] = fmaxf(u0.y + w0.y, 0.f);
            x[2] = fmaxf(u0.z + w0.z, 0.f);  x[3] = fmaxf(u0.w + w0.w, 0.f);
            x[4] = fmaxf(u1.x + w1_.x, 0.f); x[5] = fmaxf(u1.y + w1_.y, 0.f);
            x[6] = fmaxf(u1.z + w1_.z, 0.f); x[7] = fmaxf(u1.w + w1_.w, 0.f);

            uint4 hi4, lo4;
            hi4.x = pack_hi(x[0], x[1]); hi4.y = pack_hi(x[2], x[3]);
            hi4.z = pack_hi(x[4], x[5]); hi4.w = pack_hi(x[6], x[7]);
            lo4.x = pack_lo(x[0], x[1]); lo4.y = pack_lo(x[2], x[3]);
            lo4.z = pack_lo(x[4], x[5]); lo4.w = pack_lo(x[6], x[7]);

            *reinterpret_cast<uint4*>(dsm + SM_A + rbase + ((c8 ^ rx) << 4))       = hi4;
            *reinterpret_cast<uint4*>(dsm + SM_A + rbase + (((8 + c8) ^ rx) << 4)) = lo4;
        }
        __syncthreads();

        // mma phase: 12 k-steps, 2 m-tiles, 8 n-tiles
        float acc[2][8][4];
        #pragma unroll
        for (int mt = 0; mt < 2; ++mt)
            #pragma unroll
            for (int nt = 0; nt < 8; ++nt)
                #pragma unroll
                for (int q = 0; q < 4; ++q) acc[mt][nt][q] = 0.f;

        #pragma unroll
        for (int ks = 0; ks < 12; ++ks) {
            const int aks = (ks < 8) ? ks : ks - 8;      // block2 aliases block0
            uint32_t av[2][4];
            #pragma unroll
            for (int mt = 0; mt < 2; ++mt)
                LDSM_X4(av[mt], aBase[mt] + (uint32_t)(((2 * aks + g2) ^ lr) << 4));

            uint32_t bv[4][4];
            #pragma unroll
            for (int np = 0; np < 4; ++np)
                LDSM_X4_T(bv[np], bBase + (uint32_t)(ks * 2048) + nxor[np]);

            #pragma unroll
            for (int mt = 0; mt < 2; ++mt) {
                #pragma unroll
                for (int np = 0; np < 4; ++np) {
                    MMA16816(acc[mt][2 * np + 0], av[mt], bv[np][0], bv[np][1]);
                    MMA16816(acc[mt][2 * np + 1], av[mt], bv[np][2], bv[np][3]);
                }
            }
        }

        // epilogue: +b2, relu, dot w3, reduce over tig, store
        float o[2][2] = {{0.f, 0.f}, {0.f, 0.f}};
        #pragma unroll
        for (int nt = 0; nt < 8; ++nt) {
            const int col = nt * 8 + 2 * tig;
            const float2 bb = *reinterpret_cast<const float2*>(sb2 + col);
            const float2 ww = *reinterpret_cast<const float2*>(sw3 + col);
            #pragma unroll
            for (int mt = 0; mt < 2; ++mt) {
                o[mt][0] = fmaf(fmaxf(acc[mt][nt][0] + bb.x, 0.f), ww.x, o[mt][0]);
                o[mt][0] = fmaf(fmaxf(acc[mt][nt][1] + bb.y, 0.f), ww.y, o[mt][0]);
                o[mt][1] = fmaf(fmaxf(acc[mt][nt][2] + bb.x, 0.f), ww.x, o[mt][1]);
                o[mt][1] = fmaf(fmaxf(acc[mt][nt][3] + bb.y, 0.f), ww.y, o[mt][1]);
            }
        }
        #pragma unroll
        for (int mt = 0; mt < 2; ++mt) {
            #pragma unroll
            for (int rh = 0; rh < 2; ++rh) {
                float v = o[mt][rh];
                v += __shfl_xor_sync(0xffffffffu, v, 1);
                v += __shfl_xor_sync(0xffffffffu, v, 2);
                if (tig == 0) {
                    const int row = 32 * w + 16 * mt + 8 * rh + grp;
                    out[b * 128 + row] = v + b3v;
                }
            }
        }
        __syncthreads();
    }
}

// ---------------------------------------------------------------------------
extern "C" void kernel_launch(void* const* d_in, const int* in_sizes, int n_in,
                              void* d_out, int out_size) {
    const float* hidden  = (const float*)d_in[0];
    const float* actions = (const float*)d_in[1];
    const float* w1      = (const float*)d_in[2];
    const float* b1      = (const float*)d_in[3];
    const float* w2      = (const float*)d_in[4];
    const float* b2      = (const float*)d_in[5];
    const float* w3      = (const float*)d_in[6];
    const float* b3      = (const float*)d_in[7];
    float* out = (float*)d_out;

    cudaFuncSetAttribute(mma_kernel, cudaFuncAttributeMaxDynamicSharedMemorySize, SMEM_SZ);

    prep_kernel<<<BB / 16, 128>>>(hidden, actions, w1, b1);
    mma_kernel<<<GRID_MMA, 128, SMEM_SZ>>>(w2, b2, w3, b3, out);
}

// round 6
// speedup vs baseline: 1.1903x; 1.1903x over previous
#include <cuda_runtime.h>
#include <cuda_bf16.h>
#include <cstdint>

// Problem constants
#define BB   2048
#define NAG  8
#define ACT  16
#define HD   32
#define HIDN 64
#define GRID_MMA 444   // 3 CTAs per SM (148 SMs)

// Scratch (__device__ globals: allowed)
__device__ float g_u[BB * NAG * HIDN];     // u[b,g,n] = base(b)+b1 - corr(b,g)  (4 MB)
__device__ float g_w1aT[HIDN * 128];       // w1aT[k*128 + row] = W1[(g*48+32+a)*64 + k]

// ---------------------------------------------------------------------------
// bf16 split helpers (validated): hi = truncated top 16 bits, lo = rn(residual)
// ---------------------------------------------------------------------------
__device__ __forceinline__ uint32_t pack_hi(float a, float b) {
    uint32_t r;
    asm("prmt.b32 %0, %1, %2, 0x7632;" : "=r"(r)
        : "r"(__float_as_uint(a)), "r"(__float_as_uint(b)));
    return r;
}
__device__ __forceinline__ uint32_t pack_lo(float a, float b) {
    float ha = __uint_as_float(__float_as_uint(a) & 0xffff0000u);
    float hb = __uint_as_float(__float_as_uint(b) & 0xffff0000u);
    float la = a - ha, lb = b - hb;
    uint32_t r;
    asm("cvt.rn.bf16x2.f32 %0, %1, %2;" : "=r"(r) : "f"(lb), "f"(la));
    return r;
}
__device__ __forceinline__ uint32_t smem_u32(const void* p) {
    uint32_t a;
    asm("{ .reg .u64 t; cvta.to.shared.u64 t, %1; cvt.u32.u64 %0, t; }" : "=r"(a) : "l"(p));
    return a;
}
__device__ __forceinline__ void fma4(float4& acc, float s, const float4 w) {
    acc.x = fmaf(s, w.x, acc.x);
    acc.y = fmaf(s, w.y, acc.y);
    acc.z = fmaf(s, w.z, acc.z);
    acc.w = fmaf(s, w.w, acc.w);
}

#define LDSM_X4(r, addr) \
    asm volatile("ldmatrix.sync.aligned.m8n8.x4.shared.b16 {%0,%1,%2,%3}, [%4];" \
        : "=r"((r)[0]), "=r"((r)[1]), "=r"((r)[2]), "=r"((r)[3]) : "r"(addr))
#define LDSM_X4_T(r, addr) \
    asm volatile("ldmatrix.sync.aligned.m8n8.x4.trans.shared.b16 {%0,%1,%2,%3}, [%4];" \
        : "=r"((r)[0]), "=r"((r)[1]), "=r"((r)[2]), "=r"((r)[3]) : "r"(addr))
#define MMA16816(c, a, b0, b1) \
    asm volatile("mma.sync.aligned.m16n8k16.row.col.f32.bf16.bf16.f32 " \
        "{%0,%1,%2,%3}, {%4,%5,%6,%7}, {%8,%9}, {%0,%1,%2,%3};" \
        : "+f"((c)[0]), "+f"((c)[1]), "+f"((c)[2]), "+f"((c)[3]) \
        : "r"((a)[0]), "r"((a)[1]), "r"((a)[2]), "r"((a)[3]), "r"(b0), "r"(b1))

// ---------------------------------------------------------------------------
// Kernel 1: layer-1 factorization (R5 version — measured ~8.8us).
// CTA handles 16 batches; thread = (nq, bg): nq = float4 column group (16),
// bg = batch pair (8) -> 2 batches/thread (w1 reuse). One-hot actions = exact
// row gather. Emits column-major g_w1aT for the mma build phase.
// ---------------------------------------------------------------------------
__global__ void __launch_bounds__(128) prep_kernel(
    const float* __restrict__ hidden,   // [B, 8, 32]
    const float* __restrict__ actions,  // [B, 8, 16]
    const float* __restrict__ w1,       // [384, 64]
    const float* __restrict__ b1)       // [64]
{
    __shared__ float sh[16 * 256];      // staged hidden for 16 b
    __shared__ int   sidx[16 * 8];      // one-hot indices

    const int tid = threadIdx.x;
    const int b0  = blockIdx.x * 16;
    const float4* __restrict__ w1v = reinterpret_cast<const float4*>(w1);

    if (blockIdx.x == 0) {
        // column-major action-row transpose: g_w1aT[k*128 + row]
        for (int e = tid; e < HIDN * 128; e += 128) {
            const int k   = e >> 7;
            const int row = e & 127;
            const int g   = row >> 4;
            const int a   = row & 15;
            g_w1aT[e] = __ldg(w1 + (g * 48 + 32 + a) * 64 + k);
        }
    }

    // stage hidden (16 b x 256 floats = 16 KB)
    {
        const float4* hv = reinterpret_cast<const float4*>(hidden + (size_t)b0 * 256);
        float4* shv = reinterpret_cast<float4*>(sh);
        #pragma unroll
        for (int e = tid; e < 1024; e += 128) shv[e] = __ldg(hv + e);
    }

    // one-hot index per (bl, g): exact (actions are {0.0, 1.0})
    {
        const int bl = tid >> 3, g = tid & 7;
        const float* ag = actions + (size_t)(b0 + bl) * 128 + g * 16;
        float s = 0.f;
        #pragma unroll
        for (int a = 0; a < ACT; ++a) s = fmaf(__ldg(ag + a), (float)a, s);
        sidx[tid] = __float2int_rn(s);
    }
    __syncthreads();

    const int nq = tid & 15;
    const int bg = tid >> 4;

    const float4 b1v = __ldg(reinterpret_cast<const float4*>(b1) + nq);
    float4 base0 = b1v, base1 = b1v;
    const float* h0 = sh + (bg * 2 + 0) * 256;
    const float* h1 = sh + (bg * 2 + 1) * 256;

    #pragma unroll 2
    for (int j = 0; j < NAG; ++j) {
        #pragma unroll
        for (int i4 = 0; i4 < 8; ++i4) {
            const int wrow = j * 48 + i4 * 4;
            const float4 w0  = __ldg(w1v + (wrow + 0) * 16 + nq);
            const float4 w1_ = __ldg(w1v + (wrow + 1) * 16 + nq);
            const float4 w2_ = __ldg(w1v + (wrow + 2) * 16 + nq);
            const float4 w3_ = __ldg(w1v + (wrow + 3) * 16 + nq);
            const float4 ha = *reinterpret_cast<const float4*>(h0 + j * 32 + i4 * 4);
            const float4 hb = *reinterpret_cast<const float4*>(h1 + j * 32 + i4 * 4);
            fma4(base0, ha.x, w0); fma4(base0, ha.y, w1_);
            fma4(base0, ha.z, w2_); fma4(base0, ha.w, w3_);
            fma4(base1, hb.x, w0); fma4(base1, hb.y, w1_);
            fma4(base1, hb.z, w2_); fma4(base1, hb.w, w3_);
        }
    }

    #pragma unroll
    for (int bi = 0; bi < 2; ++bi) {
        const int bl = bg * 2 + bi;
        const float4 base = bi ? base1 : base0;
        float4 asum[NAG];
        float4 tot = make_float4(0.f, 0.f, 0.f, 0.f);
        #pragma unroll
        for (int g = 0; g < NAG; ++g) {
            asum[g] = __ldg(w1v + (g * 48 + 32 + sidx[bl * 8 + g]) * 16 + nq);
            tot.x += asum[g].x; tot.y += asum[g].y;
            tot.z += asum[g].z; tot.w += asum[g].w;
        }
        #pragma unroll
        for (int g = 0; g < NAG; ++g) {
            float4 v;
            v.x = base.x + tot.x - asum[g].x;
            v.y = base.y + tot.y - asum[g].y;
            v.z = base.z + tot.z - asum[g].z;
            v.w = base.w + tot.w - asum[g].w;
            *reinterpret_cast<float4*>(
                &g_u[(size_t)((b0 + bl) * NAG + g) * HIDN + nq * 4]) = v;
        }
    }
}

// ---------------------------------------------------------------------------
// Kernel 2: persistent mma.sync (HMMA bf16) GEMM + fused layers 2+3.
// EXACT R4 structure (measured 29.9us): build reads u via 16-lane-broadcast
// LDG.128 and w1aT via lane-contiguous scalar LDG (nL=4/load, L1-resident).
// A' = [x_hi | x_lo | x_hi] (block2 aliases block0), B' = [W_hi; W_hi; W_lo].
// ---------------------------------------------------------------------------
#define SM_A   0
#define SM_B   32768
#define SM_B2  57344
#define SM_W3  57600
#define SMEM_SZ 57856

__global__ void __launch_bounds__(128, 3) mma_kernel(
    const float* __restrict__ w2,   // [64, 64] (k-major)
    const float* __restrict__ b2,   // [64]
    const float* __restrict__ w3,   // [64]
    const float* __restrict__ b3,   // [1]
    float* __restrict__ out)        // [B, 128]
{
    extern __shared__ __align__(16) char dsm[];
    const uint32_t smA = smem_u32(dsm) + SM_A;
    const uint32_t smB = smem_u32(dsm) + SM_B;
    float* sb2 = reinterpret_cast<float*>(dsm + SM_B2);
    float* sw3 = reinterpret_cast<float*>(dsm + SM_W3);

    const int tid  = threadIdx.x;
    const int w    = tid >> 5;
    const int lane = tid & 31;

    if (tid < 64) {
        sb2[tid] = __ldg(b2 + tid);
        sw3[tid] = __ldg(w3 + tid);
    }
    const float b3v = __ldg(b3);

    // build B' = [W_hi; W_hi; W_lo] (192 k-rows x 64 n), xor-swizzled
    for (int e = tid; e < 192 * 32; e += 128) {
        const int kk = e >> 5;
        const int nw = e & 31;
        const int k  = kk & 63;
        const float2 f = __ldg(reinterpret_cast<const float2*>(w2 + k * 64 + 2 * nw));
        const uint32_t word = (kk < 128) ? pack_hi(f.x, f.y) : pack_lo(f.x, f.y);
        const int nc = nw >> 2;
        const uint32_t byte = (uint32_t)kk * 128u + (uint32_t)((nc ^ (kk & 7)) << 4)
                            + (uint32_t)((nw & 3) << 2);
        *reinterpret_cast<uint32_t*>(dsm + SM_B + byte) = word;
    }
    __syncthreads();

    // per-lane ldmatrix address precompute
    const int g2  = lane >> 4;
    const int gh  = (lane >> 3) & 1;
    const int lr  = lane & 7;
    const int grp = lane >> 2;
    const int tig = lane & 3;

    uint32_t aBase[2];
    #pragma unroll
    for (int mt = 0; mt < 2; ++mt)
        aBase[mt] = smA + (uint32_t)(32 * w + 16 * mt + 8 * gh + lr) * 256u;

    const int nadd = lane >> 4;
    const uint32_t bBase = smB + (uint32_t)(8 * ((lane >> 3) & 1) + lr) * 128u;
    uint32_t nxor[4];
    #pragma unroll
    for (int np = 0; np < 4; ++np)
        nxor[np] = (uint32_t)(((2 * np + nadd) ^ lr) << 4);

    const int row_ga = tid;
    const int gq     = row_ga >> 4;
    const uint32_t rbase = (uint32_t)row_ga * 256u;
    const int rx = row_ga & 7;

    for (int b = blockIdx.x; b < BB; b += GRID_MMA) {
        // build A': x1[row,k] = relu(u[b,g,k] + w1aT[k,row]); hi chunks 0-7, lo 8-15
        const float4* up = reinterpret_cast<const float4*>(g_u + (size_t)(b * NAG + gq) * HIDN);
        #pragma unroll
        for (int c8 = 0; c8 < 8; ++c8) {
            const int k0 = c8 * 8;
            const float4 u0 = __ldg(up + c8 * 2);
            const float4 u1 = __ldg(up + c8 * 2 + 1);
            float x[8];
            x[0] = u0.x; x[1] = u0.y; x[2] = u0.z; x[3] = u0.w;
            x[4] = u1.x; x[5] = u1.y; x[6] = u1.z; x[7] = u1.w;
            #pragma unroll
            for (int j = 0; j < 8; ++j)
                x[j] = fmaxf(x[j] + __ldg(g_w1aT + (k0 + j) * 128 + row_ga), 0.f);

            uint4 hi4, lo4;
            hi4.x = pack_hi(x[0], x[1]); hi4.y = pack_hi(x[2], x[3]);
            hi4.z = pack_hi(x[4], x[5]); hi4.w = pack_hi(x[6], x[7]);
            lo4.x = pack_lo(x[0], x[1]); lo4.y = pack_lo(x[2], x[3]);
            lo4.z = pack_lo(x[4], x[5]); lo4.w = pack_lo(x[6], x[7]);

            *reinterpret_cast<uint4*>(dsm + SM_A + rbase + ((c8 ^ rx) << 4))       = hi4;
            *reinterpret_cast<uint4*>(dsm + SM_A + rbase + (((8 + c8) ^ rx) << 4)) = lo4;
        }
        __syncthreads();

        // mma phase: 12 k-steps, 2 m-tiles, 8 n-tiles
        float acc[2][8][4];
        #pragma unroll
        for (int mt = 0; mt < 2; ++mt)
            #pragma unroll
            for (int nt = 0; nt < 8; ++nt)
                #pragma unroll
                for (int q = 0; q < 4; ++q) acc[mt][nt][q] = 0.f;

        #pragma unroll
        for (int ks = 0; ks < 12; ++ks) {
            const int aks = (ks < 8) ? ks : ks - 8;      // block2 aliases block0
            uint32_t av[2][4];
            #pragma unroll
            for (int mt = 0; mt < 2; ++mt)
                LDSM_X4(av[mt], aBase[mt] + (uint32_t)(((2 * aks + g2) ^ lr) << 4));

            uint32_t bv[4][4];
            #pragma unroll
            for (int np = 0; np < 4; ++np)
                LDSM_X4_T(bv[np], bBase + (uint32_t)(ks * 2048) + nxor[np]);

            #pragma unroll
            for (int mt = 0; mt < 2; ++mt) {
                #pragma unroll
                for (int np = 0; np < 4; ++np) {
                    MMA16816(acc[mt][2 * np + 0], av[mt], bv[np][0], bv[np][1]);
                    MMA16816(acc[mt][2 * np + 1], av[mt], bv[np][2], bv[np][3]);
                }
            }
        }

        // epilogue: +b2, relu, dot w3, reduce over tig, store
        float o[2][2] = {{0.f, 0.f}, {0.f, 0.f}};
        #pragma unroll
        for (int nt = 0; nt < 8; ++nt) {
            const int col = nt * 8 + 2 * tig;
            const float2 bb = *reinterpret_cast<const float2*>(sb2 + col);
            const float2 ww = *reinterpret_cast<const float2*>(sw3 + col);
            #pragma unroll
            for (int mt = 0; mt < 2; ++mt) {
                o[mt][0] = fmaf(fmaxf(acc[mt][nt][0] + bb.x, 0.f), ww.x, o[mt][0]);
                o[mt][0] = fmaf(fmaxf(acc[mt][nt][1] + bb.y, 0.f), ww.y, o[mt][0]);
                o[mt][1] = fmaf(fmaxf(acc[mt][nt][2] + bb.x, 0.f), ww.x, o[mt][1]);
                o[mt][1] = fmaf(fmaxf(acc[mt][nt][3] + bb.y, 0.f), ww.y, o[mt][1]);
            }
        }
        #pragma unroll
        for (int mt = 0; mt < 2; ++mt) {
            #pragma unroll
            for (int rh = 0; rh < 2; ++rh) {
                float v = o[mt][rh];
                v += __shfl_xor_sync(0xffffffffu, v, 1);
                v += __shfl_xor_sync(0xffffffffu, v, 2);
                if (tig == 0) {
                    const int row = 32 * w + 16 * mt + 8 * rh + grp;
                    out[b * 128 + row] = v + b3v;
                }
            }
        }
        __syncthreads();
    }
}

// ---------------------------------------------------------------------------
extern "C" void kernel_launch(void* const* d_in, const int* in_sizes, int n_in,
                              void* d_out, int out_size) {
    const float* hidden  = (const float*)d_in[0];
    const float* actions = (const float*)d_in[1];
    const float* w1      = (const float*)d_in[2];
    const float* b1      = (const float*)d_in[3];
    const float* w2      = (const float*)d_in[4];
    const float* b2      = (const float*)d_in[5];
    const float* w3      = (const float*)d_in[6];
    const float* b3      = (const float*)d_in[7];
    float* out = (float*)d_out;

    cudaFuncSetAttribute(mma_kernel, cudaFuncAttributeMaxDynamicSharedMemorySize, SMEM_SZ);

    prep_kernel<<<BB / 16, 128>>>(hidden, actions, w1, b1);
    mma_kernel<<<GRID_MMA, 128, SMEM_SZ>>>(w2, b2, w3, b3, out);
}